// round 13
// baseline (speedup 1.0000x reference)
#include <cuda_runtime.h>
#include <cstdint>

#define N_NODES 100000
#define N_EDGES 1600000
#define IN_SIZE 512
#define HID 256
#define OUTD 40
#define KSTEPS 10
#define ALPHA 0.1f
#define NB_SCAN 98   // ceil(100000/1024)

// ---------------- scratch (device globals; no allocation allowed) ----------
__device__ float g_h1[(size_t)N_NODES * HID];
__device__ float g_h0[(size_t)N_NODES * OUTD];
__device__ float g_hsA[(size_t)N_NODES * OUTD];
__device__ float g_hsB[(size_t)N_NODES * OUTD];
__device__ int   g_deg_out[N_NODES];
__device__ int   g_deg_in[N_NODES];
__device__ int   g_cursor[N_NODES];
__device__ float g_norm_src[N_NODES];
__device__ float g_norm_dst[N_NODES];
__device__ int   g_rowptr[N_NODES + 1];
__device__ int   g_col[N_EDGES];
__device__ int   g_bsum[128];
__device__ int   g_boff[128];

// ---------------- preprocessing ----------------
__global__ void zero_kernel() {
    int i = blockIdx.x * blockDim.x + threadIdx.x;
    if (i < N_NODES) {
        g_deg_out[i] = 0;
        g_deg_in[i]  = 0;
        g_cursor[i]  = 0;
    }
}

__global__ void degree_kernel(const int* __restrict__ src,
                              const int* __restrict__ dst) {
    int e = blockIdx.x * blockDim.x + threadIdx.x;
    if (e < N_EDGES) {
        atomicAdd(&g_deg_out[src[e]], 1);
        atomicAdd(&g_deg_in[dst[e]], 1);
    }
}

__global__ void norm_kernel() {
    int n = blockIdx.x * blockDim.x + threadIdx.x;
    if (n < N_NODES) {
        int dOut = g_deg_out[n]; if (dOut < 1) dOut = 1;
        int dIn  = g_deg_in[n];  if (dIn  < 1) dIn  = 1;
        g_norm_src[n] = rsqrtf((float)dOut);
        g_norm_dst[n] = rsqrtf((float)dIn);
    }
}

__device__ __forceinline__ int warp_incl_scan(int x, int lane) {
    #pragma unroll
    for (int off = 1; off < 32; off <<= 1) {
        int t = __shfl_up_sync(0xffffffffu, x, off);
        if (lane >= off) x += t;
    }
    return x;
}

// K1: per-block (1024) exclusive scan of deg_in -> rowptr (local), block totals
__global__ void scan_block_kernel() {
    __shared__ int wsums[32];
    int tid = threadIdx.x, lane = tid & 31, wid = tid >> 5;
    int i = blockIdx.x * 1024 + tid;
    int v = (i < N_NODES) ? g_deg_in[i] : 0;
    int x = warp_incl_scan(v, lane);
    if (lane == 31) wsums[wid] = x;
    __syncthreads();
    if (wid == 0) wsums[lane] = warp_incl_scan(wsums[lane], lane);
    __syncthreads();
    int incl = ((wid > 0) ? wsums[wid - 1] : 0) + x;
    if (i < N_NODES) g_rowptr[i] = incl - v;      // block-local exclusive
    if (tid == 1023) g_bsum[blockIdx.x] = incl;   // block total
}

// K2: one block (128 thr) exclusive scan of the 98 block totals
__global__ void scan_tops_kernel() {
    __shared__ int wsum[4], woff[4];
    int tid = threadIdx.x, lane = tid & 31, wid = tid >> 5;
    int v = (tid < NB_SCAN) ? g_bsum[tid] : 0;
    int x = warp_incl_scan(v, lane);
    if (lane == 31) wsum[wid] = x;
    __syncthreads();
    if (tid == 0) {
        int r = 0;
        #pragma unroll
        for (int w = 0; w < 4; w++) { woff[w] = r; r += wsum[w]; }
        g_rowptr[N_NODES] = r;   // total edge count
    }
    __syncthreads();
    if (tid < NB_SCAN) g_boff[tid] = woff[wid] + x - v;  // exclusive
}

// K3: add block offsets
__global__ void scan_add_kernel() {
    int i = blockIdx.x * 256 + threadIdx.x;
    if (i < N_NODES) g_rowptr[i] += g_boff[i >> 10];
}

__global__ void scatter_kernel(const int* __restrict__ src,
                               const int* __restrict__ dst) {
    int e = blockIdx.x * blockDim.x + threadIdx.x;
    if (e < N_EDGES) {
        int d = dst[e];
        int pos = atomicAdd(&g_cursor[d], 1);
        g_col[g_rowptr[d] + pos] = src[e];
    }
}

// ---------------- MLP layer 1 (TF32 tensor cores) ----------------
__device__ __forceinline__ uint32_t f2tf32(float f) {
    uint32_t u;
    asm("cvt.rna.tf32.f32 %0, %1;" : "=r"(u) : "f"(f));
    return u;
}

__device__ __forceinline__ void mma_tf32(float* c, const uint32_t* a,
                                         uint32_t b0, uint32_t b1) {
    asm volatile(
        "mma.sync.aligned.m16n8k8.row.col.f32.tf32.tf32.f32 "
        "{%0,%1,%2,%3}, {%4,%5,%6,%7}, {%8,%9}, {%0,%1,%2,%3};"
        : "+f"(c[0]), "+f"(c[1]), "+f"(c[2]), "+f"(c[3])
        : "r"(a[0]), "r"(a[1]), "r"(a[2]), "r"(a[3]), "r"(b0), "r"(b1));
}

#define MLP1_BK 16
#define MLP1_STR 136   // 128 + 8 pad (words)

__global__ void __launch_bounds__(256)
mlp1_mma_kernel(const float* __restrict__ X, const float* __restrict__ W1,
                const float* __restrict__ b1) {
    __shared__ __align__(16) float As[2][MLP1_BK][MLP1_STR];  // [k][m], tf32
    __shared__ __align__(16) float Bs[2][MLP1_BK][MLP1_STR];  // [k][n], tf32
    const int K = IN_SIZE, N = HID, M = N_NODES;
    int tid = threadIdx.x;
    int wid = tid >> 5, lane = tid & 31;
    int g = lane >> 2, tig = lane & 3;
    int warp_m = wid >> 1, warp_n = wid & 1;
    int m0 = blockIdx.y * 128;
    int n0 = blockIdx.x * 128;
    int m0w = warp_m * 32, n0w = warp_n * 64;

    float acc[2][8][4];
    #pragma unroll
    for (int mt = 0; mt < 2; mt++)
        #pragma unroll
        for (int j = 0; j < 8; j++)
            #pragma unroll
            for (int c = 0; c < 4; c++) acc[mt][j][c] = 0.f;

    int am  = tid & 127;
    int akq = tid >> 7;
    const int nkt = K / MLP1_BK;   // 32

    {
        int row = m0 + am;
        #pragma unroll
        for (int q = 0; q < 2; q++) {
            int kq = akq + q * 2;
            float4 f = make_float4(0.f, 0.f, 0.f, 0.f);
            if (row < M) f = *(const float4*)(X + (long)row * K + kq * 4);
            As[0][kq * 4 + 0][am] = __uint_as_float(f2tf32(f.x));
            As[0][kq * 4 + 1][am] = __uint_as_float(f2tf32(f.y));
            As[0][kq * 4 + 2][am] = __uint_as_float(f2tf32(f.z));
            As[0][kq * 4 + 3][am] = __uint_as_float(f2tf32(f.w));
        }
        #pragma unroll
        for (int q = 0; q < 2; q++) {
            int idx = tid + q * 256;
            int kr = idx >> 5, c = idx & 31;
            float4 f = *(const float4*)(W1 + (long)kr * N + n0 + c * 4);
            float4 t;
            t.x = __uint_as_float(f2tf32(f.x));
            t.y = __uint_as_float(f2tf32(f.y));
            t.z = __uint_as_float(f2tf32(f.z));
            t.w = __uint_as_float(f2tf32(f.w));
            *(float4*)&Bs[0][kr][c * 4] = t;
        }
    }
    __syncthreads();

    for (int kt = 0; kt < nkt; kt++) {
        int cur = kt & 1, nxt = cur ^ 1;
        float4 ar[2], br[2];
        bool has_next = (kt + 1 < nkt);
        if (has_next) {
            int kbase = (kt + 1) * MLP1_BK;
            int row = m0 + am;
            #pragma unroll
            for (int q = 0; q < 2; q++) {
                int kq = akq + q * 2;
                ar[q] = make_float4(0.f, 0.f, 0.f, 0.f);
                if (row < M)
                    ar[q] = *(const float4*)(X + (long)row * K + kbase + kq * 4);
            }
            #pragma unroll
            for (int q = 0; q < 2; q++) {
                int idx = tid + q * 256;
                int kr = idx >> 5, c = idx & 31;
                br[q] = *(const float4*)(W1 + (long)(kbase + kr) * N + n0 + c * 4);
            }
        }
        #pragma unroll
        for (int ks = 0; ks < 2; ks++) {
            int kb = ks * 8;
            uint32_t a[2][4];
            #pragma unroll
            for (int mt = 0; mt < 2; mt++) {
                int mm = m0w + mt * 16 + g;
                a[mt][0] = __float_as_uint(As[cur][kb + tig][mm]);
                a[mt][1] = __float_as_uint(As[cur][kb + tig][mm + 8]);
                a[mt][2] = __float_as_uint(As[cur][kb + tig + 4][mm]);
                a[mt][3] = __float_as_uint(As[cur][kb + tig + 4][mm + 8]);
            }
            #pragma unroll
            for (int j = 0; j < 8; j++) {
                int nn = n0w + j * 8 + g;
                uint32_t b0 = __float_as_uint(Bs[cur][kb + tig][nn]);
                uint32_t b1r = __float_as_uint(Bs[cur][kb + tig + 4][nn]);
                mma_tf32(acc[0][j], a[0], b0, b1r);
                mma_tf32(acc[1][j], a[1], b0, b1r);
            }
        }
        if (has_next) {
            #pragma unroll
            for (int q = 0; q < 2; q++) {
                int kq = akq + q * 2;
                As[nxt][kq * 4 + 0][am] = __uint_as_float(f2tf32(ar[q].x));
                As[nxt][kq * 4 + 1][am] = __uint_as_float(f2tf32(ar[q].y));
                As[nxt][kq * 4 + 2][am] = __uint_as_float(f2tf32(ar[q].z));
                As[nxt][kq * 4 + 3][am] = __uint_as_float(f2tf32(ar[q].w));
            }
            #pragma unroll
            for (int q = 0; q < 2; q++) {
                int idx = tid + q * 256;
                int kr = idx >> 5, c = idx & 31;
                float4 t;
                t.x = __uint_as_float(f2tf32(br[q].x));
                t.y = __uint_as_float(f2tf32(br[q].y));
                t.z = __uint_as_float(f2tf32(br[q].z));
                t.w = __uint_as_float(f2tf32(br[q].w));
                *(float4*)&Bs[nxt][kr][c * 4] = t;
            }
        }
        __syncthreads();
    }

    #pragma unroll
    for (int mt = 0; mt < 2; mt++) {
        #pragma unroll
        for (int j = 0; j < 8; j++) {
            int col0 = n0 + n0w + j * 8 + tig * 2;
            float bb0 = __ldg(b1 + col0);
            float bb1 = __ldg(b1 + col0 + 1);
            int r0 = m0 + m0w + mt * 16 + g;
            int r1 = r0 + 8;
            if (r0 < M) {
                g_h1[(long)r0 * HID + col0]     = fmaxf(acc[mt][j][0] + bb0, 0.f);
                g_h1[(long)r0 * HID + col0 + 1] = fmaxf(acc[mt][j][1] + bb1, 0.f);
            }
            if (r1 < M) {
                g_h1[(long)r1 * HID + col0]     = fmaxf(acc[mt][j][2] + bb0, 0.f);
                g_h1[(long)r1 * HID + col0 + 1] = fmaxf(acc[mt][j][3] + bb1, 0.f);
            }
        }
    }
}

// ---------------- MLP layer 2 + init ----------------
__global__ void __launch_bounds__(320)
mlp2_kernel(const float* __restrict__ W2, const float* __restrict__ b2) {
    __shared__ float sh[32 * 264];
    int tid = threadIdx.x;
    int brow = blockIdx.x * 32;
    for (int i = tid; i < 2048; i += 320) {
        int r = i >> 6, c4 = i & 63;
        float4 v = *(const float4*)(g_h1 + (long)(brow + r) * HID + c4 * 4);
        sh[r * 264 + c4 * 4 + 0] = v.x;
        sh[r * 264 + c4 * 4 + 1] = v.y;
        sh[r * 264 + c4 * 4 + 2] = v.z;
        sh[r * 264 + c4 * 4 + 3] = v.w;
    }
    __syncthreads();
    int r  = tid / 10;
    int cg = tid % 10;
    float4 acc = make_float4(0.f, 0.f, 0.f, 0.f);
    #pragma unroll 4
    for (int k = 0; k < HID; k++) {
        float a = sh[r * 264 + k];
        float4 w = __ldg((const float4*)(W2 + (long)k * OUTD + cg * 4));
        acc.x += a * w.x;
        acc.y += a * w.y;
        acc.z += a * w.z;
        acc.w += a * w.w;
    }
    int n = brow + r;
    float ns = g_norm_src[n];
    float4 bb = __ldg((const float4*)(b2 + cg * 4));
    float4 h0v;
    h0v.x = acc.x + bb.x;
    h0v.y = acc.y + bb.y;
    h0v.z = acc.z + bb.z;
    h0v.w = acc.w + bb.w;
    *(float4*)(g_h0 + (long)n * OUTD + cg * 4) = h0v;
    float4 hsv;
    hsv.x = h0v.x * ns; hsv.y = h0v.y * ns; hsv.z = h0v.z * ns; hsv.w = h0v.w * ns;
    *(float4*)(g_hsA + (long)n * OUTD + cg * 4) = hsv;
}

// ---------------- propagation step ----------------
// 4-deep software pipeline: 4 independent col loads then 4 independent
// float4 gathers per iteration -> MLP_eff ~4 instead of a serial
// col->gather->col dependent chain (R11 post-mortem: prop was latency-bound).
__global__ void __launch_bounds__(256)
prop_kernel(int odd, int last, float* __restrict__ out) {
    const float* hs_in  = odd ? g_hsB : g_hsA;
    float*       hs_out = odd ? g_hsA : g_hsB;
    int gwarp = (blockIdx.x * blockDim.x + threadIdx.x) >> 5;
    int lane = threadIdx.x & 31;
    if (gwarp >= N_NODES) return;
    int rs = g_rowptr[gwarp];
    int re = g_rowptr[gwarp + 1];
    float4 acc = make_float4(0.f, 0.f, 0.f, 0.f);
    bool active = lane < 10;
    int e = rs;
    for (; e + 4 <= re; e += 4) {
        int s0 = __ldg(&g_col[e]);
        int s1 = __ldg(&g_col[e + 1]);
        int s2 = __ldg(&g_col[e + 2]);
        int s3 = __ldg(&g_col[e + 3]);
        if (active) {
            float4 v0 = __ldg((const float4*)(hs_in + (long)s0 * OUTD) + lane);
            float4 v1 = __ldg((const float4*)(hs_in + (long)s1 * OUTD) + lane);
            float4 v2 = __ldg((const float4*)(hs_in + (long)s2 * OUTD) + lane);
            float4 v3 = __ldg((const float4*)(hs_in + (long)s3 * OUTD) + lane);
            acc.x += (v0.x + v1.x) + (v2.x + v3.x);
            acc.y += (v0.y + v1.y) + (v2.y + v3.y);
            acc.z += (v0.z + v1.z) + (v2.z + v3.z);
            acc.w += (v0.w + v1.w) + (v2.w + v3.w);
        }
    }
    for (; e < re; ++e) {
        int s = __ldg(&g_col[e]);
        if (active) {
            float4 v = __ldg((const float4*)(hs_in + (long)s * OUTD) + lane);
            acc.x += v.x; acc.y += v.y; acc.z += v.z; acc.w += v.w;
        }
    }
    if (active) {
        float nd = g_norm_dst[gwarp];
        float ns = g_norm_src[gwarp];
        const float oma = 1.0f - ALPHA;
        long base4 = (long)gwarp * 10 + lane;
        float4 h0v = ((const float4*)g_h0)[base4];
        float4 v;
        v.x = oma * acc.x * nd + ALPHA * h0v.x;
        v.y = oma * acc.y * nd + ALPHA * h0v.y;
        v.z = oma * acc.z * nd + ALPHA * h0v.z;
        v.w = oma * acc.w * nd + ALPHA * h0v.w;
        if (last) {
            ((float4*)out)[base4] = v;
        } else {
            float4 sv;
            sv.x = v.x * ns; sv.y = v.y * ns; sv.z = v.z * ns; sv.w = v.w * ns;
            ((float4*)hs_out)[base4] = sv;
        }
    }
}

// ---------------- launch --------------------------------------------------
extern "C" void kernel_launch(void* const* d_in, const int* in_sizes, int n_in,
                              void* d_out, int out_size) {
    const float* X   = (const float*)d_in[0];
    const int*   src = (const int*)d_in[1];
    const int*   dst = (const int*)d_in[2];
    const float* W1  = (const float*)d_in[3];
    const float* b1  = (const float*)d_in[4];
    const float* W2  = (const float*)d_in[5];
    const float* b2  = (const float*)d_in[6];
    float* out = (float*)d_out;

    // NOTE: mlp1 at launch position 4 — the ncu capture lands on the 4th
    // launch (observed R5+R11), so the next profile measures the TF32 GEMM.
    // mlp1 depends only on X/W1/b1; g_h1 is first read by mlp2 later.
    zero_kernel<<<(N_NODES + 255) / 256, 256>>>();
    degree_kernel<<<(N_EDGES + 255) / 256, 256>>>(src, dst);
    norm_kernel<<<(N_NODES + 255) / 256, 256>>>();
    {
        dim3 grid(HID / 128, (N_NODES + 127) / 128);
        mlp1_mma_kernel<<<grid, 256>>>(X, W1, b1);
    }
    scan_block_kernel<<<NB_SCAN, 1024>>>();
    scan_tops_kernel<<<1, 128>>>();
    scan_add_kernel<<<(N_NODES + 255) / 256, 256>>>();
    scatter_kernel<<<(N_EDGES + 255) / 256, 256>>>(src, dst);
    mlp2_kernel<<<N_NODES / 32, 320>>>(W2, b2);

    // 10 APPNP steps, ping-pong hs buffers; last writes d_out only
    int prop_blocks = (N_NODES * 32 + 255) / 256;
    for (int k = 0; k < KSTEPS; ++k) {
        prop_kernel<<<prop_blocks, 256>>>(k & 1, k == KSTEPS - 1, out);
    }
}